// round 8
// baseline (speedup 1.0000x reference)
#include <cuda_runtime.h>
#include <math_constants.h>

#define BT      32768   // B*T rows
#define ZC      512     // input channels
#define DD      256     // embed dim
#define KCODES  8192    // codebook entries
#define NPART   1024    // loss partials

// scratch (allocation-free requirement -> __device__ globals)
__device__ float g_h[BT * DD];        // 32 MB: projected h
__device__ float g_cnorm[KCODES];     // fl32(||e_k||^2), fp64-accumulated
__device__ float g_hnorm[BT];         // fl32(||h_row||^2), fp64-accumulated
__device__ int   g_idx[BT];           // argmin index per row
__device__ float g_part[NPART];       // loss partial sums

// ---------------------------------------------------------------------------
// K1: h = x @ W + b   (fp32 FFMA, 128x128 tile, kchunk 16, double-buffered)
// ---------------------------------------------------------------------------
__global__ __launch_bounds__(256, 2)
void k_gemm_h(const float* __restrict__ x, const float* __restrict__ W,
              const float* __restrict__ b) {
    __shared__ float As[2][16][128];   // [buf][k][m]  (transposed store)
    __shared__ float Bs[2][16][128];   // [buf][k][n]
    const int tid = threadIdx.x;
    const int tx = tid & 15, ty = tid >> 4;
    const int m0 = blockIdx.y * 128;
    const int n0 = blockIdx.x * 128;

    float acc[8][8];
#pragma unroll
    for (int i = 0; i < 8; i++)
#pragma unroll
        for (int j = 0; j < 8; j++) acc[i][j] = 0.f;

    const int ar  = tid >> 2;        // 0..63
    const int ac4 = tid & 3;
    const int bkr = tid >> 5;        // 0..7
    const int bc4 = tid & 31;

    // prologue: chunk 0 -> buf 0
    float4 a0 = *(const float4*)&x[(m0 + ar)      * ZC + ac4 * 4];
    float4 a1 = *(const float4*)&x[(m0 + ar + 64) * ZC + ac4 * 4];
    float4 w0 = *(const float4*)&W[(bkr)     * DD + n0 + bc4 * 4];
    float4 w1 = *(const float4*)&W[(bkr + 8) * DD + n0 + bc4 * 4];
    As[0][ac4 * 4 + 0][ar]      = a0.x; As[0][ac4 * 4 + 1][ar]      = a0.y;
    As[0][ac4 * 4 + 2][ar]      = a0.z; As[0][ac4 * 4 + 3][ar]      = a0.w;
    As[0][ac4 * 4 + 0][ar + 64] = a1.x; As[0][ac4 * 4 + 1][ar + 64] = a1.y;
    As[0][ac4 * 4 + 2][ar + 64] = a1.z; As[0][ac4 * 4 + 3][ar + 64] = a1.w;
    *(float4*)&Bs[0][bkr][bc4 * 4]     = w0;
    *(float4*)&Bs[0][bkr + 8][bc4 * 4] = w1;
    __syncthreads();

    int pb = 0;
    for (int c = 0; c < ZC / 16; c++) {
        const bool pre = (c < ZC / 16 - 1);
        if (pre) {
            int k0 = (c + 1) * 16;
            a0 = *(const float4*)&x[(m0 + ar)      * ZC + k0 + ac4 * 4];
            a1 = *(const float4*)&x[(m0 + ar + 64) * ZC + k0 + ac4 * 4];
            w0 = *(const float4*)&W[(k0 + bkr)     * DD + n0 + bc4 * 4];
            w1 = *(const float4*)&W[(k0 + bkr + 8) * DD + n0 + bc4 * 4];
        }
#pragma unroll
        for (int kk = 0; kk < 16; kk++) {
            float4 av0 = *(const float4*)&As[pb][kk][ty * 8];
            float4 av1 = *(const float4*)&As[pb][kk][ty * 8 + 4];
            float4 bv0 = *(const float4*)&Bs[pb][kk][tx * 8];
            float4 bv1 = *(const float4*)&Bs[pb][kk][tx * 8 + 4];
            float a[8] = {av0.x, av0.y, av0.z, av0.w, av1.x, av1.y, av1.z, av1.w};
            float cc[8] = {bv0.x, bv0.y, bv0.z, bv0.w, bv1.x, bv1.y, bv1.z, bv1.w};
#pragma unroll
            for (int i = 0; i < 8; i++)
#pragma unroll
                for (int j = 0; j < 8; j++) acc[i][j] = fmaf(a[i], cc[j], acc[i][j]);
        }
        if (pre) {
            int nb = pb ^ 1;
            As[nb][ac4 * 4 + 0][ar]      = a0.x; As[nb][ac4 * 4 + 1][ar]      = a0.y;
            As[nb][ac4 * 4 + 2][ar]      = a0.z; As[nb][ac4 * 4 + 3][ar]      = a0.w;
            As[nb][ac4 * 4 + 0][ar + 64] = a1.x; As[nb][ac4 * 4 + 1][ar + 64] = a1.y;
            As[nb][ac4 * 4 + 2][ar + 64] = a1.z; As[nb][ac4 * 4 + 3][ar + 64] = a1.w;
            *(float4*)&Bs[nb][bkr][bc4 * 4]     = w0;
            *(float4*)&Bs[nb][bkr + 8][bc4 * 4] = w1;
            __syncthreads();
            pb = nb;
        }
    }
    float bias[8];
#pragma unroll
    for (int j = 0; j < 8; j++) bias[j] = b[n0 + tx * 8 + j];
#pragma unroll
    for (int i = 0; i < 8; i++) {
        int row = m0 + ty * 8 + i;
#pragma unroll
        for (int j = 0; j < 8; j++)
            g_h[row * DD + n0 + tx * 8 + j] = acc[i][j] + bias[j];
    }
}

// ---------------------------------------------------------------------------
// K2: B_k = fl32( ||e_k||^2 )  — fp64 accumulate (correctly rounded)
// ---------------------------------------------------------------------------
__global__ __launch_bounds__(256)
void k_cnorm(const float* __restrict__ cb) {
    int code = blockIdx.x * 8 + (threadIdx.x >> 5);
    int lane = threadIdx.x & 31;
    const float* row = cb + code * DD;
    double s = 0.0;
#pragma unroll
    for (int i = 0; i < DD / 32; i++) {
        double v = (double)row[lane + i * 32];
        s = fma(v, v, s);
    }
#pragma unroll
    for (int o = 16; o > 0; o >>= 1) s += __shfl_xor_sync(0xffffffffu, s, o);
    if (lane == 0) g_cnorm[code] = (float)s;
}

// ---------------------------------------------------------------------------
// K2b: A_row = fl32( ||h_row||^2 )  — fp64 accumulate
// ---------------------------------------------------------------------------
__global__ __launch_bounds__(256)
void k_hnorm() {
    int row  = blockIdx.x * 8 + (threadIdx.x >> 5);
    int lane = threadIdx.x & 31;
    const float* hr = g_h + (long)row * DD;
    double s = 0.0;
#pragma unroll
    for (int i = 0; i < DD / 32; i++) {
        double v = (double)hr[lane + i * 32];
        s = fma(v, v, s);
    }
#pragma unroll
    for (int o = 16; o > 0; o >>= 1) s += __shfl_xor_sync(0xffffffffu, s, o);
    if (lane == 0) g_hnorm[row] = (float)s;
}

// ---------------------------------------------------------------------------
// K3: argmin_k  fl32( fl32(A + B_k) - 2*M_k )
//     Double-buffered smem, ONE barrier per 16-chunk, prefetch across the
//     codebook-tile boundary. fp32 SGEMM for M; lower-index tie-break.
// ---------------------------------------------------------------------------
__global__ __launch_bounds__(256, 2)
void k_argmin(const float* __restrict__ cb) {
    __shared__ float As[2][16][128];   // [buf][d][m]  h tile (transposed)
    __shared__ float Bs[2][16][128];   // [buf][d][c]  codebook tile (transposed)
    const int tid = threadIdx.x;
    const int tx = tid & 15, ty = tid >> 4;
    const int m0 = blockIdx.x * 128;

    float best[8];
    int   bidx[8];
    float hn[8];
#pragma unroll
    for (int i = 0; i < 8; i++) {
        best[i] = CUDART_INF_F; bidx[i] = 0;
        hn[i] = g_hnorm[m0 + ty * 8 + i];
    }

    const int r  = tid >> 2;   // 0..63
    const int c4 = tid & 3;

    // prologue: (kt=0, d0=0) -> buf 0
    float4 a0 = *(const float4*)&g_h[(m0 + r)      * DD + c4 * 4];
    float4 a1 = *(const float4*)&g_h[(m0 + r + 64) * DD + c4 * 4];
    float4 w0 = *(const float4*)&cb[(r)       * DD + c4 * 4];
    float4 w1 = *(const float4*)&cb[(r + 64)  * DD + c4 * 4];
    As[0][c4 * 4 + 0][r]      = a0.x; As[0][c4 * 4 + 1][r]      = a0.y;
    As[0][c4 * 4 + 2][r]      = a0.z; As[0][c4 * 4 + 3][r]      = a0.w;
    As[0][c4 * 4 + 0][r + 64] = a1.x; As[0][c4 * 4 + 1][r + 64] = a1.y;
    As[0][c4 * 4 + 2][r + 64] = a1.z; As[0][c4 * 4 + 3][r + 64] = a1.w;
    Bs[0][c4 * 4 + 0][r]      = w0.x; Bs[0][c4 * 4 + 1][r]      = w0.y;
    Bs[0][c4 * 4 + 2][r]      = w0.z; Bs[0][c4 * 4 + 3][r]      = w0.w;
    Bs[0][c4 * 4 + 0][r + 64] = w1.x; Bs[0][c4 * 4 + 1][r + 64] = w1.y;
    Bs[0][c4 * 4 + 2][r + 64] = w1.z; Bs[0][c4 * 4 + 3][r + 64] = w1.w;
    __syncthreads();

    int pb = 0;
    for (int kt = 0; kt < KCODES; kt += 128) {
        float acc[8][8];
#pragma unroll
        for (int i = 0; i < 8; i++)
#pragma unroll
            for (int j = 0; j < 8; j++) acc[i][j] = 0.f;

        for (int c = 0; c < DD / 16; c++) {
            // next chunk: within this tile, or chunk 0 of the next codebook tile
            int nkt = kt, nd0 = (c + 1) * 16;
            if (c == DD / 16 - 1) { nkt = kt + 128; nd0 = 0; }
            const bool pre = (nkt < KCODES);
            if (pre) {
                a0 = *(const float4*)&g_h[(m0 + r)       * DD + nd0 + c4 * 4];
                a1 = *(const float4*)&g_h[(m0 + r + 64)  * DD + nd0 + c4 * 4];
                w0 = *(const float4*)&cb[(nkt + r)       * DD + nd0 + c4 * 4];
                w1 = *(const float4*)&cb[(nkt + r + 64)  * DD + nd0 + c4 * 4];
            }
#pragma unroll
            for (int kk = 0; kk < 16; kk++) {
                float4 av0 = *(const float4*)&As[pb][kk][ty * 8];
                float4 av1 = *(const float4*)&As[pb][kk][ty * 8 + 4];
                float4 bv0 = *(const float4*)&Bs[pb][kk][tx * 8];
                float4 bv1 = *(const float4*)&Bs[pb][kk][tx * 8 + 4];
                float a[8] = {av0.x, av0.y, av0.z, av0.w, av1.x, av1.y, av1.z, av1.w};
                float cc[8] = {bv0.x, bv0.y, bv0.z, bv0.w, bv1.x, bv1.y, bv1.z, bv1.w};
#pragma unroll
                for (int i = 0; i < 8; i++)
#pragma unroll
                    for (int j = 0; j < 8; j++) acc[i][j] = fmaf(a[i], cc[j], acc[i][j]);
            }
            if (pre) {
                int nb = pb ^ 1;
                As[nb][c4 * 4 + 0][r]      = a0.x; As[nb][c4 * 4 + 1][r]      = a0.y;
                As[nb][c4 * 4 + 2][r]      = a0.z; As[nb][c4 * 4 + 3][r]      = a0.w;
                As[nb][c4 * 4 + 0][r + 64] = a1.x; As[nb][c4 * 4 + 1][r + 64] = a1.y;
                As[nb][c4 * 4 + 2][r + 64] = a1.z; As[nb][c4 * 4 + 3][r + 64] = a1.w;
                Bs[nb][c4 * 4 + 0][r]      = w0.x; Bs[nb][c4 * 4 + 1][r]      = w0.y;
                Bs[nb][c4 * 4 + 2][r]      = w0.z; Bs[nb][c4 * 4 + 3][r]      = w0.w;
                Bs[nb][c4 * 4 + 0][r + 64] = w1.x; Bs[nb][c4 * 4 + 1][r + 64] = w1.y;
                Bs[nb][c4 * 4 + 2][r + 64] = w1.z; Bs[nb][c4 * 4 + 3][r + 64] = w1.w;
                __syncthreads();
                pb = nb;
            }
        }
        // epilogue with the reference's two fp32 roundings at magnitude ~257:
        //   t = fl32(A + B_k);  s = fl32(t - 2*M_k)
#pragma unroll
        for (int j = 0; j < 8; j++) {
            int code = kt + tx * 8 + j;
            float cn = g_cnorm[code];
#pragma unroll
            for (int i = 0; i < 8; i++) {
                float t = __fadd_rn(hn[i], cn);
                float s = __fmaf_rn(-2.0f, acc[i][j], t);
                if (s < best[i]) { best[i] = s; bidx[i] = code; }
            }
        }
    }
    // reduce across the 16 tx threads sharing each row; tie -> lower index
#pragma unroll
    for (int i = 0; i < 8; i++) {
        float v = best[i];
        int   bi = bidx[i];
#pragma unroll
        for (int off = 8; off >= 1; off >>= 1) {
            float ov = __shfl_xor_sync(0xffffffffu, v, off);
            int   oi = __shfl_xor_sync(0xffffffffu, bi, off);
            if (ov < v || (ov == v && oi < bi)) { v = ov; bi = oi; }
        }
        if (tx == 0) g_idx[m0 + ty * 8 + i] = bi;
    }
}

// ---------------------------------------------------------------------------
// K4: gather zq -> out, partial loss sums  (deterministic: fixed order)
// ---------------------------------------------------------------------------
__global__ __launch_bounds__(256)
void k_gather(const float* __restrict__ cb, float* __restrict__ out) {
    __shared__ float red[256];
    float lsum = 0.f;
    const int total = BT * DD;
    for (int e = blockIdx.x * 256 + threadIdx.x; e < total; e += NPART * 256) {
        int row = e >> 8;
        int d = e & (DD - 1);
        int c = g_idx[row];
        float zq = cb[c * DD + d];
        float hh = g_h[e];
        out[e] = zq;                         // STE forward value == zq
        float df = zq - hh;
        lsum = fmaf(df, df, lsum);
    }
    red[threadIdx.x] = lsum;
    __syncthreads();
    for (int o = 128; o > 0; o >>= 1) {
        if (threadIdx.x < o) red[threadIdx.x] += red[threadIdx.x + o];
        __syncthreads();
    }
    if (threadIdx.x == 0) g_part[blockIdx.x] = red[0];
}

// ---------------------------------------------------------------------------
// K5: final loss reduce -> out[out_size-1]
// ---------------------------------------------------------------------------
__global__ __launch_bounds__(256)
void k_loss(float* __restrict__ out, int out_size) {
    __shared__ float red[256];
    float s = 0.f;
    for (int i = threadIdx.x; i < NPART; i += 256) s += g_part[i];
    red[threadIdx.x] = s;
    __syncthreads();
    for (int o = 128; o > 0; o >>= 1) {
        if (threadIdx.x < o) red[threadIdx.x] += red[threadIdx.x + o];
        __syncthreads();
    }
    if (threadIdx.x == 0)
        out[out_size - 1] = 1.25f * red[0] / (float)(BT * DD);
}

// ---------------------------------------------------------------------------
extern "C" void kernel_launch(void* const* d_in, const int* in_sizes, int n_in,
                              void* d_out, int out_size) {
    const float* x  = (const float*)d_in[0];   // [8,4096,1,512]
    const float* W  = (const float*)d_in[1];   // [512,256]
    const float* b  = (const float*)d_in[2];   // [256]
    const float* cb = (const float*)d_in[3];   // [8192,256]
    float* out = (float*)d_out;

    k_gemm_h<<<dim3(DD / 128, BT / 128), 256>>>(x, W, b);
    k_cnorm<<<KCODES / 8, 256>>>(cb);
    k_hnorm<<<BT / 8, 256>>>();
    k_argmin<<<BT / 128, 256>>>(cb);
    k_gather<<<NPART, 256>>>(cb, out);
    k_loss<<<1, 256>>>(out, out_size);
}

// round 10
// speedup vs baseline: 1.4545x; 1.4545x over previous
#include <cuda_runtime.h>
#include <math_constants.h>

#define BT      32768   // B*T rows
#define ZC      512     // input channels
#define DD      256     // embed dim
#define KCODES  8192    // codebook entries
#define NPART   1024    // loss partials
#define MAXC    8       // max candidates per row
#define MARGIN  2.5e-4f // candidate margin (scan noise ~1e-5)

// scratch (allocation-free requirement -> __device__ globals)
__device__ float g_h[BT * DD];        // 32 MB: projected h
__device__ float g_cnorm[KCODES];     // fl32(||e_k||^2), fp64-accumulated
__device__ float g_hnorm[BT];         // fl32(||h_row||^2), fp64-accumulated
__device__ int   g_idx[BT];           // argmin index per row
__device__ float g_part[NPART];       // loss partial sums
__device__ int   g_cand_cnt[BT];      // candidate count per row
__device__ int   g_cand[BT][MAXC];    // candidate code ids per row

// RNA round to TF32 grid (matches cvt.rna.tf32.f32)
__device__ __forceinline__ float tf32hi(float f) {
    unsigned u = __float_as_uint(f);
    u = (u + 0x1000u) & 0xFFFFE000u;
    return __uint_as_float(u);
}

__device__ __forceinline__ void mma_tf32(float* c, const unsigned* a, const unsigned* b) {
    asm volatile(
        "mma.sync.aligned.m16n8k8.row.col.f32.tf32.tf32.f32 "
        "{%0,%1,%2,%3}, {%4,%5,%6,%7}, {%8,%9}, {%0,%1,%2,%3};\n"
        : "+f"(c[0]), "+f"(c[1]), "+f"(c[2]), "+f"(c[3])
        : "r"(a[0]), "r"(a[1]), "r"(a[2]), "r"(a[3]), "r"(b[0]), "r"(b[1]));
}

// ---------------------------------------------------------------------------
// K1: h = x @ W + b   (fp32 FFMA, 128x128 tile, kchunk 16)  [round-4 proven]
// ---------------------------------------------------------------------------
__global__ __launch_bounds__(256, 2)
void k_gemm_h(const float* __restrict__ x, const float* __restrict__ W,
              const float* __restrict__ b) {
    __shared__ float As[16][128];
    __shared__ float Bs[16][128];
    const int tid = threadIdx.x;
    const int tx = tid & 15, ty = tid >> 4;
    const int m0 = blockIdx.y * 128;
    const int n0 = blockIdx.x * 128;

    float acc[8][8];
#pragma unroll
    for (int i = 0; i < 8; i++)
#pragma unroll
        for (int j = 0; j < 8; j++) acc[i][j] = 0.f;

    const int ar  = tid >> 2;
    const int ac4 = tid & 3;
    const int bkr = tid >> 5;
    const int bc4 = tid & 31;

    for (int k0 = 0; k0 < ZC; k0 += 16) {
        float4 a0 = *(const float4*)&x[(m0 + ar)      * ZC + k0 + ac4 * 4];
        float4 a1 = *(const float4*)&x[(m0 + ar + 64) * ZC + k0 + ac4 * 4];
        float4 w0 = *(const float4*)&W[(k0 + bkr)     * DD + n0 + bc4 * 4];
        float4 w1 = *(const float4*)&W[(k0 + bkr + 8) * DD + n0 + bc4 * 4];
        __syncthreads();
        As[ac4 * 4 + 0][ar]      = a0.x; As[ac4 * 4 + 1][ar]      = a0.y;
        As[ac4 * 4 + 2][ar]      = a0.z; As[ac4 * 4 + 3][ar]      = a0.w;
        As[ac4 * 4 + 0][ar + 64] = a1.x; As[ac4 * 4 + 1][ar + 64] = a1.y;
        As[ac4 * 4 + 2][ar + 64] = a1.z; As[ac4 * 4 + 3][ar + 64] = a1.w;
        *(float4*)&Bs[bkr][bc4 * 4]     = w0;
        *(float4*)&Bs[bkr + 8][bc4 * 4] = w1;
        __syncthreads();
#pragma unroll
        for (int kk = 0; kk < 16; kk++) {
            float4 av0 = *(const float4*)&As[kk][ty * 8];
            float4 av1 = *(const float4*)&As[kk][ty * 8 + 4];
            float4 bv0 = *(const float4*)&Bs[kk][tx * 8];
            float4 bv1 = *(const float4*)&Bs[kk][tx * 8 + 4];
            float a[8] = {av0.x, av0.y, av0.z, av0.w, av1.x, av1.y, av1.z, av1.w};
            float c[8] = {bv0.x, bv0.y, bv0.z, bv0.w, bv1.x, bv1.y, bv1.z, bv1.w};
#pragma unroll
            for (int i = 0; i < 8; i++)
#pragma unroll
                for (int j = 0; j < 8; j++) acc[i][j] = fmaf(a[i], c[j], acc[i][j]);
        }
    }
    float bias[8];
#pragma unroll
    for (int j = 0; j < 8; j++) bias[j] = b[n0 + tx * 8 + j];
#pragma unroll
    for (int i = 0; i < 8; i++) {
        int row = m0 + ty * 8 + i;
#pragma unroll
        for (int j = 0; j < 8; j++)
            g_h[row * DD + n0 + tx * 8 + j] = acc[i][j] + bias[j];
    }
}

// ---------------------------------------------------------------------------
// K2 / K2b: fp64-accumulated squared norms
// ---------------------------------------------------------------------------
__global__ __launch_bounds__(256)
void k_cnorm(const float* __restrict__ cb) {
    int code = blockIdx.x * 8 + (threadIdx.x >> 5);
    int lane = threadIdx.x & 31;
    const float* row = cb + code * DD;
    double s = 0.0;
#pragma unroll
    for (int i = 0; i < DD / 32; i++) {
        double v = (double)row[lane + i * 32];
        s = fma(v, v, s);
    }
#pragma unroll
    for (int o = 16; o > 0; o >>= 1) s += __shfl_xor_sync(0xffffffffu, s, o);
    if (lane == 0) g_cnorm[code] = (float)s;
}

__global__ __launch_bounds__(256)
void k_hnorm() {
    int row  = blockIdx.x * 8 + (threadIdx.x >> 5);
    int lane = threadIdx.x & 31;
    const float* hr = g_h + (long)row * DD;
    double s = 0.0;
#pragma unroll
    for (int i = 0; i < DD / 32; i++) {
        double v = (double)hr[lane + i * 32];
        s = fma(v, v, s);
    }
#pragma unroll
    for (int o = 16; o > 0; o >>= 1) s += __shfl_xor_sync(0xffffffffu, s, o);
    if (lane == 0) g_hnorm[row] = (float)s;
}

// ---------------------------------------------------------------------------
// K3: tensor-core candidate scan (2xTF32 split: hi*hi + hi*lo + lo*hi)
//     Block: 256 thr (8 warps), 128 rows/block, code tiles of 128, KC=16.
//     Warp w: rows (w&3)*32 .. +32 (two m16 tiles), codes (w>>2)*64 (8 n8).
// ---------------------------------------------------------------------------
__global__ __launch_bounds__(256)
void k_scan_tc(const float* __restrict__ cb) {
    __shared__ float Hhi[128][20];
    __shared__ float Hlo[128][20];
    __shared__ float Chi[128][20];
    __shared__ float Clo[128][20];
    __shared__ int   rowMinB[128];
    __shared__ int   s_cnt[128];
    __shared__ int   s_list[128][MAXC];

    const int tid  = threadIdx.x;
    const int lane = tid & 31;
    const int w    = tid >> 5;
    const int g    = lane >> 2;       // group 0..7
    const int tg   = lane & 3;        // thread-in-group 0..3
    const int mrow = (w & 3) * 32;    // warp row base (local)
    const int ncol = (w >> 2) * 64;   // warp code base (within tile)
    const int m0   = blockIdx.x * 128;

    if (tid < 128) { rowMinB[tid] = 0x7f800000; s_cnt[tid] = 0; }

    // per-thread top-2 for 4 row-slots: rows mrow+g, mrow+8+g, mrow+16+g, mrow+24+g
    float tv1[4], tv2[4];
    unsigned tpk[4];                  // packed: low16 = idx1, high16 = idx2
#pragma unroll
    for (int s = 0; s < 4; s++) { tv1[s] = CUDART_INF_F; tv2[s] = CUDART_INF_F; tpk[s] = 0; }

    float hnv[4];
#pragma unroll
    for (int s = 0; s < 4; s++) hnv[s] = g_hnorm[m0 + mrow + s * 8 + g];

    // smem fill indices: thread loads 2 float4 of h and 2 of cb per chunk
    const int fr  = tid >> 1;         // row/code 0..127
    const int fq  = (tid & 1) * 2;    // which float4 pair (quads fq, fq+1)

    for (int kt = 0; kt < KCODES; kt += 128) {
        float acc[2][8][4];
#pragma unroll
        for (int mt = 0; mt < 2; mt++)
#pragma unroll
            for (int nt = 0; nt < 8; nt++)
#pragma unroll
                for (int q = 0; q < 4; q++) acc[mt][nt][q] = 0.f;

        for (int ch = 0; ch < DD / 16; ch++) {
            int d0 = ch * 16;
            float4 hv0 = *(const float4*)&g_h[(m0 + fr) * DD + d0 + fq * 4];
            float4 hv1 = *(const float4*)&g_h[(m0 + fr) * DD + d0 + fq * 4 + 4];
            float4 cv0 = *(const float4*)&cb[(kt + fr) * DD + d0 + fq * 4];
            float4 cv1 = *(const float4*)&cb[(kt + fr) * DD + d0 + fq * 4 + 4];
            __syncthreads();
            {
                float hx[8] = {hv0.x, hv0.y, hv0.z, hv0.w, hv1.x, hv1.y, hv1.z, hv1.w};
                float cx[8] = {cv0.x, cv0.y, cv0.z, cv0.w, cv1.x, cv1.y, cv1.z, cv1.w};
#pragma unroll
                for (int i = 0; i < 8; i++) {
                    float hh = tf32hi(hx[i]);
                    Hhi[fr][fq * 4 + i] = hh;
                    Hlo[fr][fq * 4 + i] = hx[i] - hh;
                    float ce = tf32hi(cx[i]);
                    Chi[fr][fq * 4 + i] = ce;
                    Clo[fr][fq * 4 + i] = cx[i] - ce;
                }
            }
            __syncthreads();
#pragma unroll
            for (int k8 = 0; k8 < 2; k8++) {
                int kb = k8 * 8;
                unsigned Ahi[2][4], Alo[2][4];
#pragma unroll
                for (int mt = 0; mt < 2; mt++) {
                    int R = mrow + mt * 16;
                    Ahi[mt][0] = __float_as_uint(Hhi[R + g][kb + tg]);
                    Ahi[mt][1] = __float_as_uint(Hhi[R + 8 + g][kb + tg]);
                    Ahi[mt][2] = __float_as_uint(Hhi[R + g][kb + tg + 4]);
                    Ahi[mt][3] = __float_as_uint(Hhi[R + 8 + g][kb + tg + 4]);
                    Alo[mt][0] = __float_as_uint(Hlo[R + g][kb + tg]);
                    Alo[mt][1] = __float_as_uint(Hlo[R + 8 + g][kb + tg]);
                    Alo[mt][2] = __float_as_uint(Hlo[R + g][kb + tg + 4]);
                    Alo[mt][3] = __float_as_uint(Hlo[R + 8 + g][kb + tg + 4]);
                }
#pragma unroll
                for (int nt = 0; nt < 8; nt++) {
                    int C = ncol + nt * 8 + g;
                    unsigned Bhi[2], Blo[2];
                    Bhi[0] = __float_as_uint(Chi[C][kb + tg]);
                    Bhi[1] = __float_as_uint(Chi[C][kb + tg + 4]);
                    Blo[0] = __float_as_uint(Clo[C][kb + tg]);
                    Blo[1] = __float_as_uint(Clo[C][kb + tg + 4]);
#pragma unroll
                    for (int mt = 0; mt < 2; mt++) {
                        mma_tf32(acc[mt][nt], Ahi[mt], Bhi);
                        mma_tf32(acc[mt][nt], Ahi[mt], Blo);
                        mma_tf32(acc[mt][nt], Alo[mt], Bhi);
                    }
                }
            }
        }
        // epilogue: approx scores, streaming top-2 per row-slot
#pragma unroll
        for (int nt = 0; nt < 8; nt++) {
            int code0 = kt + ncol + nt * 8 + 2 * tg;
            float cn0 = g_cnorm[code0];
            float cn1 = g_cnorm[code0 + 1];
#pragma unroll
            for (int mt = 0; mt < 2; mt++) {
#pragma unroll
                for (int q = 0; q < 4; q++) {
                    int sl = mt * 2 + (q >> 1);           // row slot
                    float cn = (q & 1) ? cn1 : cn0;
                    int   cd = code0 + (q & 1);
                    float s = fmaf(-2.f, acc[mt][nt][q], hnv[sl] + cn);
                    if (s < tv1[sl]) {
                        tv2[sl] = tv1[sl];
                        tpk[sl] = ((tpk[sl] & 0xffffu) << 16) | (unsigned)cd;
                        tv1[sl] = s;
                    } else if (s < tv2[sl]) {
                        tv2[sl] = s;
                        tpk[sl] = (tpk[sl] & 0xffffu) | ((unsigned)cd << 16);
                    }
                }
            }
        }
    }
    __syncthreads();   // rowMinB/s_cnt init visible; all tiles done
    // per-row min (positive floats -> int-bit monotone)
#pragma unroll
    for (int s = 0; s < 4; s++) {
        int rl = mrow + s * 8 + g;
        atomicMin(&rowMinB[rl], __float_as_int(tv1[s]));
    }
    __syncthreads();
#pragma unroll
    for (int s = 0; s < 4; s++) {
        int rl = mrow + s * 8 + g;
        float thr = __int_as_float(rowMinB[rl]) + MARGIN;
        if (tv1[s] <= thr) {
            int sl = atomicAdd(&s_cnt[rl], 1);
            if (sl < MAXC) s_list[rl][sl] = (int)(tpk[s] & 0xffffu);
        }
        if (tv2[s] <= thr) {
            int sl = atomicAdd(&s_cnt[rl], 1);
            if (sl < MAXC) s_list[rl][sl] = (int)(tpk[s] >> 16);
        }
    }
    __syncthreads();
    if (tid < 128) {
        int n = s_cnt[tid]; if (n > MAXC) n = MAXC;
        g_cand_cnt[m0 + tid] = n;
        for (int k = 0; k < n; k++) g_cand[m0 + tid][k] = s_list[tid][k];
    }
}

// ---------------------------------------------------------------------------
// K4: refine — exact round-4 numerics: ascending-d fp32 fmaf dot (single
//     accumulator), t = fl(hn+cn), s = fl(t - 2*dot); lower-index ties.
//     One warp per row; lane c handles candidate c.
// ---------------------------------------------------------------------------
__global__ __launch_bounds__(256)
void k_refine(const float* __restrict__ cb) {
    int row  = blockIdx.x * 8 + (threadIdx.x >> 5);
    int lane = threadIdx.x & 31;
    int n = g_cand_cnt[row];
    if (n <= 1) {
        if (lane == 0) g_idx[row] = (n == 1) ? g_cand[row][0] : 0;
        return;
    }
    float s  = CUDART_INF_F;
    int   bi = 0x7fffffff;
    if (lane < n) {
        int code = g_cand[row][lane];
        const float* hr = g_h + (long)row * DD;
        const float* er = cb + (long)code * DD;
        float acc = 0.f;
        for (int d = 0; d < DD; d++) acc = __fmaf_rn(hr[d], er[d], acc);
        float t = __fadd_rn(g_hnorm[row], g_cnorm[code]);
        s = __fmaf_rn(-2.f, acc, t);
        bi = code;
    }
#pragma unroll
    for (int off = 16; off >= 1; off >>= 1) {
        float ov = __shfl_xor_sync(0xffffffffu, s, off);
        int   oi = __shfl_xor_sync(0xffffffffu, bi, off);
        if (ov < s || (ov == s && oi < bi)) { s = ov; bi = oi; }
    }
    if (lane == 0) g_idx[row] = bi;
}

// ---------------------------------------------------------------------------
// K5: gather zq -> out, partial loss sums
// ---------------------------------------------------------------------------
__global__ __launch_bounds__(256)
void k_gather(const float* __restrict__ cb, float* __restrict__ out) {
    __shared__ float red[256];
    float lsum = 0.f;
    const int total = BT * DD;
    for (int e = blockIdx.x * 256 + threadIdx.x; e < total; e += NPART * 256) {
        int row = e >> 8;
        int d = e & (DD - 1);
        int c = g_idx[row];
        float zq = cb[c * DD + d];
        float hh = g_h[e];
        out[e] = zq;
        float df = zq - hh;
        lsum = fmaf(df, df, lsum);
    }
    red[threadIdx.x] = lsum;
    __syncthreads();
    for (int o = 128; o > 0; o >>= 1) {
        if (threadIdx.x < o) red[threadIdx.x] += red[threadIdx.x + o];
        __syncthreads();
    }
    if (threadIdx.x == 0) g_part[blockIdx.x] = red[0];
}

// ---------------------------------------------------------------------------
// K6: final loss reduce
// ---------------------------------------------------------------------------
__global__ __launch_bounds__(256)
void k_loss(float* __restrict__ out, int out_size) {
    __shared__ float red[256];
    float s = 0.f;
    for (int i = threadIdx.x; i < NPART; i += 256) s += g_part[i];
    red[threadIdx.x] = s;
    __syncthreads();
    for (int o = 128; o > 0; o >>= 1) {
        if (threadIdx.x < o) red[threadIdx.x] += red[threadIdx.x + o];
        __syncthreads();
    }
    if (threadIdx.x == 0)
        out[out_size - 1] = 1.25f * red[0] / (float)(BT * DD);
}

// ---------------------------------------------------------------------------
extern "C" void kernel_launch(void* const* d_in, const int* in_sizes, int n_in,
                              void* d_out, int out_size) {
    const float* x  = (const float*)d_in[0];   // [8,4096,1,512]
    const float* W  = (const float*)d_in[1];   // [512,256]
    const float* b  = (const float*)d_in[2];   // [256]
    const float* cb = (const float*)d_in[3];   // [8192,256]
    float* out = (float*)d_out;

    k_gemm_h<<<dim3(DD / 128, BT / 128), 256>>>(x, W, b);
    k_cnorm<<<KCODES / 8, 256>>>(cb);
    k_hnorm<<<BT / 8, 256>>>();
    k_scan_tc<<<BT / 128, 256>>>(cb);
    k_refine<<<BT / 8, 256>>>(cb);
    k_gather<<<NPART, 256>>>(cb, out);
    k_loss<<<1, 256>>>(out, out_size);
}

// round 15
// speedup vs baseline: 1.8717x; 1.2868x over previous
#include <cuda_runtime.h>
#include <math_constants.h>

#define BT      32768   // B*T rows
#define ZC      512     // input channels
#define DD      256     // embed dim
#define KCODES  8192    // codebook entries
#define NPART   1024    // loss partials
#define MAXC    8       // max candidates per row
#define MARGIN  2.5e-4f // candidate margin (scan noise ~1e-5)

// scratch (allocation-free requirement -> __device__ globals)
__device__ float g_h[BT * DD];        // 32 MB: projected h
__device__ float g_cnorm[KCODES];     // fl32(||e_k||^2), fp64-accumulated
__device__ float g_hnorm[BT];         // fl32(||h_row||^2), fp64-accumulated
__device__ int   g_idx[BT];           // argmin index per row
__device__ float g_part[NPART];       // loss partial sums
__device__ int   g_cand_cnt[BT];      // candidate count per row
__device__ int   g_cand[BT][MAXC];    // candidate code ids per row

// RNA round to TF32 grid (matches cvt.rna.tf32.f32)
__device__ __forceinline__ float tf32hi(float f) {
    unsigned u = __float_as_uint(f);
    u = (u + 0x1000u) & 0xFFFFE000u;
    return __uint_as_float(u);
}

__device__ __forceinline__ void mma_tf32(float* c, const unsigned* a, const unsigned* b) {
    asm volatile(
        "mma.sync.aligned.m16n8k8.row.col.f32.tf32.tf32.f32 "
        "{%0,%1,%2,%3}, {%4,%5,%6,%7}, {%8,%9}, {%0,%1,%2,%3};\n"
        : "+f"(c[0]), "+f"(c[1]), "+f"(c[2]), "+f"(c[3])
        : "r"(a[0]), "r"(a[1]), "r"(a[2]), "r"(a[3]), "r"(b[0]), "r"(b[1]));
}

// ldmatrix x4 (b16-aliased): loads four 8x4-b32 quadrants; thread i of each
// quadrant receives b32 element (row i>>2, col i&3) — the tf32 mma layout.
__device__ __forceinline__ void ldsm4(unsigned* r, unsigned addr) {
    asm volatile(
        "ldmatrix.sync.aligned.m8n8.x4.shared.b16 {%0,%1,%2,%3}, [%4];\n"
        : "=r"(r[0]), "=r"(r[1]), "=r"(r[2]), "=r"(r[3]) : "r"(addr));
}

__device__ __forceinline__ unsigned smem_u32(const void* p) {
    return (unsigned)__cvta_generic_to_shared(p);
}

// ---------------------------------------------------------------------------
// K1: h = x @ W + b   (fp32 FFMA, 128x128 tile, kchunk 16)  [round-4 proven]
// ---------------------------------------------------------------------------
__global__ __launch_bounds__(256, 2)
void k_gemm_h(const float* __restrict__ x, const float* __restrict__ W,
              const float* __restrict__ b) {
    __shared__ float As[16][128];
    __shared__ float Bs[16][128];
    const int tid = threadIdx.x;
    const int tx = tid & 15, ty = tid >> 4;
    const int m0 = blockIdx.y * 128;
    const int n0 = blockIdx.x * 128;

    float acc[8][8];
#pragma unroll
    for (int i = 0; i < 8; i++)
#pragma unroll
        for (int j = 0; j < 8; j++) acc[i][j] = 0.f;

    const int ar  = tid >> 2;
    const int ac4 = tid & 3;
    const int bkr = tid >> 5;
    const int bc4 = tid & 31;

    for (int k0 = 0; k0 < ZC; k0 += 16) {
        float4 a0 = *(const float4*)&x[(m0 + ar)      * ZC + k0 + ac4 * 4];
        float4 a1 = *(const float4*)&x[(m0 + ar + 64) * ZC + k0 + ac4 * 4];
        float4 w0 = *(const float4*)&W[(k0 + bkr)     * DD + n0 + bc4 * 4];
        float4 w1 = *(const float4*)&W[(k0 + bkr + 8) * DD + n0 + bc4 * 4];
        __syncthreads();
        As[ac4 * 4 + 0][ar]      = a0.x; As[ac4 * 4 + 1][ar]      = a0.y;
        As[ac4 * 4 + 2][ar]      = a0.z; As[ac4 * 4 + 3][ar]      = a0.w;
        As[ac4 * 4 + 0][ar + 64] = a1.x; As[ac4 * 4 + 1][ar + 64] = a1.y;
        As[ac4 * 4 + 2][ar + 64] = a1.z; As[ac4 * 4 + 3][ar + 64] = a1.w;
        *(float4*)&Bs[bkr][bc4 * 4]     = w0;
        *(float4*)&Bs[bkr + 8][bc4 * 4] = w1;
        __syncthreads();
#pragma unroll
        for (int kk = 0; kk < 16; kk++) {
            float4 av0 = *(const float4*)&As[kk][ty * 8];
            float4 av1 = *(const float4*)&As[kk][ty * 8 + 4];
            float4 bv0 = *(const float4*)&Bs[kk][tx * 8];
            float4 bv1 = *(const float4*)&Bs[kk][tx * 8 + 4];
            float a[8] = {av0.x, av0.y, av0.z, av0.w, av1.x, av1.y, av1.z, av1.w};
            float c[8] = {bv0.x, bv0.y, bv0.z, bv0.w, bv1.x, bv1.y, bv1.z, bv1.w};
#pragma unroll
            for (int i = 0; i < 8; i++)
#pragma unroll
                for (int j = 0; j < 8; j++) acc[i][j] = fmaf(a[i], c[j], acc[i][j]);
        }
    }
    float bias[8];
#pragma unroll
    for (int j = 0; j < 8; j++) bias[j] = b[n0 + tx * 8 + j];
#pragma unroll
    for (int i = 0; i < 8; i++) {
        int row = m0 + ty * 8 + i;
#pragma unroll
        for (int j = 0; j < 8; j++)
            g_h[row * DD + n0 + tx * 8 + j] = acc[i][j] + bias[j];
    }
}

// ---------------------------------------------------------------------------
// K2 / K2b: fp64-accumulated squared norms
// ---------------------------------------------------------------------------
__global__ __launch_bounds__(256)
void k_cnorm(const float* __restrict__ cb) {
    int code = blockIdx.x * 8 + (threadIdx.x >> 5);
    int lane = threadIdx.x & 31;
    const float* row = cb + code * DD;
    double s = 0.0;
#pragma unroll
    for (int i = 0; i < DD / 32; i++) {
        double v = (double)row[lane + i * 32];
        s = fma(v, v, s);
    }
#pragma unroll
    for (int o = 16; o > 0; o >>= 1) s += __shfl_xor_sync(0xffffffffu, s, o);
    if (lane == 0) g_cnorm[code] = (float)s;
}

__global__ __launch_bounds__(256)
void k_hnorm() {
    int row  = blockIdx.x * 8 + (threadIdx.x >> 5);
    int lane = threadIdx.x & 31;
    const float* hr = g_h + (long)row * DD;
    double s = 0.0;
#pragma unroll
    for (int i = 0; i < DD / 32; i++) {
        double v = (double)hr[lane + i * 32];
        s = fma(v, v, s);
    }
#pragma unroll
    for (int o = 16; o > 0; o >>= 1) s += __shfl_xor_sync(0xffffffffu, s, o);
    if (lane == 0) g_hnorm[row] = (float)s;
}

// ---------------------------------------------------------------------------
// K3: tensor-core candidate scan (2xTF32 split), ldmatrix fragments,
//     forced 2 CTAs/SM. Numerics/mapping identical to round-10 version.
// ---------------------------------------------------------------------------
__global__ __launch_bounds__(256, 2)
void k_scan_tc(const float* __restrict__ cb) {
    __shared__ float Hhi[128][20];
    __shared__ float Hlo[128][20];
    __shared__ float Chi[128][20];
    __shared__ float Clo[128][20];
    __shared__ int   rowMinB[128];
    __shared__ int   s_cnt[128];
    __shared__ int   s_list[128][MAXC];

    const int tid  = threadIdx.x;
    const int lane = tid & 31;
    const int w    = tid >> 5;
    const int g    = lane >> 2;       // group 0..7
    const int tg   = lane & 3;        // thread-in-group 0..3
    const int mrow = (w & 3) * 32;    // warp row base (local)
    const int ncol = (w >> 2) * 64;   // warp code base (within tile)
    const int m0   = blockIdx.x * 128;

    if (tid < 128) { rowMinB[tid] = 0x7f800000; s_cnt[tid] = 0; }

    float tv1[4], tv2[4];
    unsigned tpk[4];
#pragma unroll
    for (int s = 0; s < 4; s++) { tv1[s] = CUDART_INF_F; tv2[s] = CUDART_INF_F; tpk[s] = 0; }

    float hnv[4];
#pragma unroll
    for (int s = 0; s < 4; s++) hnv[s] = g_hnorm[m0 + mrow + s * 8 + g];

    // smem fill indices: thread loads 2 float4 of h and 2 of cb per chunk
    const int fr = tid >> 1;
    const int fq = (tid & 1) * 2;

    // ldmatrix addresses (per-lane, fixed for the whole kernel; +32B for kb=8)
    // A quadrants: row = base + ((lane>>3)&1)*8 + (lane&7), col = ((lane>>4)&1)*4
    const int aRow = ((lane >> 3) & 1) * 8 + (lane & 7);
    const int aCol = ((lane >> 4) & 1) * 4;
    // B quadrants: row = base + ((lane>>4)&1)*8 + (lane&7), col = ((lane>>3)&1)*4
    const int bRow = ((lane >> 4) & 1) * 8 + (lane & 7);
    const int bCol = ((lane >> 3) & 1) * 4;

    const unsigned shAhi0 = smem_u32(&Hhi[mrow + aRow][aCol]);
    const unsigned shAhi1 = shAhi0 + 16 * 20 * 4;
    const unsigned shAlo0 = smem_u32(&Hlo[mrow + aRow][aCol]);
    const unsigned shAlo1 = shAlo0 + 16 * 20 * 4;
    const unsigned shBhi0 = smem_u32(&Chi[ncol + bRow][bCol]);
    const unsigned shBlo0 = smem_u32(&Clo[ncol + bRow][bCol]);

    for (int kt = 0; kt < KCODES; kt += 128) {
        float acc[2][8][4];
#pragma unroll
        for (int mt = 0; mt < 2; mt++)
#pragma unroll
            for (int nt = 0; nt < 8; nt++)
#pragma unroll
                for (int q = 0; q < 4; q++) acc[mt][nt][q] = 0.f;

        for (int ch = 0; ch < DD / 16; ch++) {
            int d0 = ch * 16;
            float4 hv0 = *(const float4*)&g_h[(m0 + fr) * DD + d0 + fq * 4];
            float4 hv1 = *(const float4*)&g_h[(m0 + fr) * DD + d0 + fq * 4 + 4];
            float4 cv0 = *(const float4*)&cb[(kt + fr) * DD + d0 + fq * 4];
            float4 cv1 = *(const float4*)&cb[(kt + fr) * DD + d0 + fq * 4 + 4];
            __syncthreads();
            {
                float hx[8] = {hv0.x, hv0.y, hv0.z, hv0.w, hv1.x, hv1.y, hv1.z, hv1.w};
                float cx[8] = {cv0.x, cv0.y, cv0.z, cv0.w, cv1.x, cv1.y, cv1.z, cv1.w};
#pragma unroll
                for (int i = 0; i < 8; i++) {
                    float hh = tf32hi(hx[i]);
                    Hhi[fr][fq * 4 + i] = hh;
                    Hlo[fr][fq * 4 + i] = hx[i] - hh;
                    float ce = tf32hi(cx[i]);
                    Chi[fr][fq * 4 + i] = ce;
                    Clo[fr][fq * 4 + i] = cx[i] - ce;
                }
            }
            __syncthreads();
#pragma unroll
            for (int k8 = 0; k8 < 2; k8++) {
                const unsigned ko = k8 * 32;    // kb=8 -> +32 bytes
                unsigned Ahi[2][4], Alo[2][4];
                ldsm4(Ahi[0], shAhi0 + ko);
                ldsm4(Ahi[1], shAhi1 + ko);
                ldsm4(Alo[0], shAlo0 + ko);
                ldsm4(Alo[1], shAlo1 + ko);
#pragma unroll
                for (int ntp = 0; ntp < 4; ntp++) {
                    const unsigned no = ntp * 16 * 20 * 4;   // +16 codes
                    unsigned Bhi[4], Blo[4];
                    ldsm4(Bhi, shBhi0 + no + ko);
                    ldsm4(Blo, shBlo0 + no + ko);
#pragma unroll
                    for (int mt = 0; mt < 2; mt++) {
                        mma_tf32(acc[mt][2 * ntp],     Ahi[mt], Bhi);
                        mma_tf32(acc[mt][2 * ntp],     Ahi[mt], Blo);
                        mma_tf32(acc[mt][2 * ntp],     Alo[mt], Bhi);
                        mma_tf32(acc[mt][2 * ntp + 1], Ahi[mt], Bhi + 2);
                        mma_tf32(acc[mt][2 * ntp + 1], Ahi[mt], Blo + 2);
                        mma_tf32(acc[mt][2 * ntp + 1], Alo[mt], Bhi + 2);
                    }
                }
            }
        }
        // epilogue: approx scores, streaming top-2 per row-slot (unchanged)
#pragma unroll
        for (int nt = 0; nt < 8; nt++) {
            int code0 = kt + ncol + nt * 8 + 2 * tg;
            float cn0 = g_cnorm[code0];
            float cn1 = g_cnorm[code0 + 1];
#pragma unroll
            for (int mt = 0; mt < 2; mt++) {
#pragma unroll
                for (int q = 0; q < 4; q++) {
                    int sl = mt * 2 + (q >> 1);
                    float cn = (q & 1) ? cn1 : cn0;
                    int   cd = code0 + (q & 1);
                    float s = fmaf(-2.f, acc[mt][nt][q], hnv[sl] + cn);
                    if (s < tv1[sl]) {
                        tv2[sl] = tv1[sl];
                        tpk[sl] = ((tpk[sl] & 0xffffu) << 16) | (unsigned)cd;
                        tv1[sl] = s;
                    } else if (s < tv2[sl]) {
                        tv2[sl] = s;
                        tpk[sl] = (tpk[sl] & 0xffffu) | ((unsigned)cd << 16);
                    }
                }
            }
        }
    }
    __syncthreads();
#pragma unroll
    for (int s = 0; s < 4; s++) {
        int rl = mrow + s * 8 + g;
        atomicMin(&rowMinB[rl], __float_as_int(tv1[s]));
    }
    __syncthreads();
#pragma unroll
    for (int s = 0; s < 4; s++) {
        int rl = mrow + s * 8 + g;
        float thr = __int_as_float(rowMinB[rl]) + MARGIN;
        if (tv1[s] <= thr) {
            int sl = atomicAdd(&s_cnt[rl], 1);
            if (sl < MAXC) s_list[rl][sl] = (int)(tpk[s] & 0xffffu);
        }
        if (tv2[s] <= thr) {
            int sl = atomicAdd(&s_cnt[rl], 1);
            if (sl < MAXC) s_list[rl][sl] = (int)(tpk[s] >> 16);
        }
    }
    __syncthreads();
    if (tid < 128) {
        int n = s_cnt[tid]; if (n > MAXC) n = MAXC;
        g_cand_cnt[m0 + tid] = n;
        for (int k = 0; k < n; k++) g_cand[m0 + tid][k] = s_list[tid][k];
    }
}

// ---------------------------------------------------------------------------
// K4: refine — exact round-4 numerics (unchanged)
// ---------------------------------------------------------------------------
__global__ __launch_bounds__(256)
void k_refine(const float* __restrict__ cb) {
    int row  = blockIdx.x * 8 + (threadIdx.x >> 5);
    int lane = threadIdx.x & 31;
    int n = g_cand_cnt[row];
    if (n <= 1) {
        if (lane == 0) g_idx[row] = (n == 1) ? g_cand[row][0] : 0;
        return;
    }
    float s  = CUDART_INF_F;
    int   bi = 0x7fffffff;
    if (lane < n) {
        int code = g_cand[row][lane];
        const float* hr = g_h + (long)row * DD;
        const float* er = cb + (long)code * DD;
        float acc = 0.f;
        for (int d = 0; d < DD; d++) acc = __fmaf_rn(hr[d], er[d], acc);
        float t = __fadd_rn(g_hnorm[row], g_cnorm[code]);
        s = __fmaf_rn(-2.f, acc, t);
        bi = code;
    }
#pragma unroll
    for (int off = 16; off >= 1; off >>= 1) {
        float ov = __shfl_xor_sync(0xffffffffu, s, off);
        int   oi = __shfl_xor_sync(0xffffffffu, bi, off);
        if (ov < s || (ov == s && oi < bi)) { s = ov; bi = oi; }
    }
    if (lane == 0) g_idx[row] = bi;
}

// ---------------------------------------------------------------------------
// K5: gather zq -> out, partial loss sums
// ---------------------------------------------------------------------------
__global__ __launch_bounds__(256)
void k_gather(const float* __restrict__ cb, float* __restrict__ out) {
    __shared__ float red[256];
    float lsum = 0.f;
    const int total = BT * DD;
    for (int e = blockIdx.x * 256 + threadIdx.x; e < total; e += NPART * 256) {
        int row = e >> 8;
        int d = e & (DD - 1);
        int c = g_idx[row];
        float zq = cb[c * DD + d];
        float hh = g_h[e];
        out[e] = zq;
        float df = zq - hh;
        lsum = fmaf(df, df, lsum);
    }
    red[threadIdx.x] = lsum;
    __syncthreads();
    for (int o = 128; o > 0; o >>= 1) {
        if (threadIdx.x < o) red[threadIdx.x] += red[threadIdx.x + o];
        __syncthreads();
    }
    if (threadIdx.x == 0) g_part[blockIdx.x] = red[0];
}

// ---------------------------------------------------------------------------
// K6: final loss reduce
// ---------------------------------------------------------------------------
__global__ __launch_bounds__(256)
void k_loss(float* __restrict__ out, int out_size) {
    __shared__ float red[256];
    float s = 0.f;
    for (int i = threadIdx.x; i < NPART; i += 256) s += g_part[i];
    red[threadIdx.x] = s;
    __syncthreads();
    for (int o = 128; o > 0; o >>= 1) {
        if (threadIdx.x < o) red[threadIdx.x] += red[threadIdx.x + o];
        __syncthreads();
    }
    if (threadIdx.x == 0)
        out[out_size - 1] = 1.25f * red[0] / (float)(BT * DD);
}

// ---------------------------------------------------------------------------
extern "C" void kernel_launch(void* const* d_in, const int* in_sizes, int n_in,
                              void* d_out, int out_size) {
    const float* x  = (const float*)d_in[0];   // [8,4096,1,512]
    const float* W  = (const float*)d_in[1];   // [512,256]
    const float* b  = (const float*)d_in[2];   // [256]
    const float* cb = (const float*)d_in[3];   // [8192,256]
    float* out = (float*)d_out;

    k_gemm_h<<<dim3(DD / 128, BT / 128), 256>>>(x, W, b);
    k_cnorm<<<KCODES / 8, 256>>>(cb);
    k_hnorm<<<BT / 8, 256>>>();
    k_scan_tc<<<BT / 128, 256>>>(cb);
    k_refine<<<BT / 8, 256>>>(cb);
    k_gather<<<NPART, 256>>>(cb, out);
    k_loss<<<1, 256>>>(out, out_size);
}

// round 16
// speedup vs baseline: 3.8259x; 2.0441x over previous
#include <cuda_runtime.h>
#include <math_constants.h>

#define BT      32768   // B*T rows
#define ZC      512     // input channels
#define DD      256     // embed dim
#define KCODES  8192    // codebook entries
#define NPART   1024    // loss partials
#define MAXC    8       // max candidates per row
#define MARGIN  4e-3f   // candidate margin (hi-only TF32 scan noise sigma ~7e-4)

// scratch (allocation-free requirement -> __device__ globals)
__device__ float g_h[BT * DD];        // 32 MB: projected h
__device__ float g_cnorm[KCODES];     // fl32(||e_k||^2), fp64-accumulated
__device__ float g_hnorm[BT];         // fl32(||h_row||^2), fp64-accumulated
__device__ int   g_idx[BT];           // argmin index per row
__device__ float g_part[NPART];       // loss partial sums
__device__ int   g_cand_cnt[BT];      // candidate count per row
__device__ int   g_cand[BT][MAXC];    // candidate code ids per row

// RNA round to TF32 grid (matches cvt.rna.tf32.f32)
__device__ __forceinline__ float tf32hi(float f) {
    unsigned u = __float_as_uint(f);
    u = (u + 0x1000u) & 0xFFFFE000u;
    return __uint_as_float(u);
}

__device__ __forceinline__ void mma_tf32(float* c, const unsigned* a, const unsigned* b) {
    asm volatile(
        "mma.sync.aligned.m16n8k8.row.col.f32.tf32.tf32.f32 "
        "{%0,%1,%2,%3}, {%4,%5,%6,%7}, {%8,%9}, {%0,%1,%2,%3};\n"
        : "+f"(c[0]), "+f"(c[1]), "+f"(c[2]), "+f"(c[3])
        : "r"(a[0]), "r"(a[1]), "r"(a[2]), "r"(a[3]), "r"(b[0]), "r"(b[1]));
}

// ldmatrix x4 (b16-aliased): four 8x4-b32 quadrants in tf32-mma layout.
__device__ __forceinline__ void ldsm4(unsigned* r, unsigned addr) {
    asm volatile(
        "ldmatrix.sync.aligned.m8n8.x4.shared.b16 {%0,%1,%2,%3}, [%4];\n"
        : "=r"(r[0]), "=r"(r[1]), "=r"(r[2]), "=r"(r[3]) : "r"(addr));
}

__device__ __forceinline__ unsigned smem_u32(const void* p) {
    return (unsigned)__cvta_generic_to_shared(p);
}

// ---------------------------------------------------------------------------
// K1: h = x @ W + b   (fp32 FFMA, 128x128 tile, kchunk 16)  [round-4 proven]
// ---------------------------------------------------------------------------
__global__ __launch_bounds__(256, 2)
void k_gemm_h(const float* __restrict__ x, const float* __restrict__ W,
              const float* __restrict__ b) {
    __shared__ float As[16][128];
    __shared__ float Bs[16][128];
    const int tid = threadIdx.x;
    const int tx = tid & 15, ty = tid >> 4;
    const int m0 = blockIdx.y * 128;
    const int n0 = blockIdx.x * 128;

    float acc[8][8];
#pragma unroll
    for (int i = 0; i < 8; i++)
#pragma unroll
        for (int j = 0; j < 8; j++) acc[i][j] = 0.f;

    const int ar  = tid >> 2;
    const int ac4 = tid & 3;
    const int bkr = tid >> 5;
    const int bc4 = tid & 31;

    for (int k0 = 0; k0 < ZC; k0 += 16) {
        float4 a0 = *(const float4*)&x[(m0 + ar)      * ZC + k0 + ac4 * 4];
        float4 a1 = *(const float4*)&x[(m0 + ar + 64) * ZC + k0 + ac4 * 4];
        float4 w0 = *(const float4*)&W[(k0 + bkr)     * DD + n0 + bc4 * 4];
        float4 w1 = *(const float4*)&W[(k0 + bkr + 8) * DD + n0 + bc4 * 4];
        __syncthreads();
        As[ac4 * 4 + 0][ar]      = a0.x; As[ac4 * 4 + 1][ar]      = a0.y;
        As[ac4 * 4 + 2][ar]      = a0.z; As[ac4 * 4 + 3][ar]      = a0.w;
        As[ac4 * 4 + 0][ar + 64] = a1.x; As[ac4 * 4 + 1][ar + 64] = a1.y;
        As[ac4 * 4 + 2][ar + 64] = a1.z; As[ac4 * 4 + 3][ar + 64] = a1.w;
        *(float4*)&Bs[bkr][bc4 * 4]     = w0;
        *(float4*)&Bs[bkr + 8][bc4 * 4] = w1;
        __syncthreads();
#pragma unroll
        for (int kk = 0; kk < 16; kk++) {
            float4 av0 = *(const float4*)&As[kk][ty * 8];
            float4 av1 = *(const float4*)&As[kk][ty * 8 + 4];
            float4 bv0 = *(const float4*)&Bs[kk][tx * 8];
            float4 bv1 = *(const float4*)&Bs[kk][tx * 8 + 4];
            float a[8] = {av0.x, av0.y, av0.z, av0.w, av1.x, av1.y, av1.z, av1.w};
            float c[8] = {bv0.x, bv0.y, bv0.z, bv0.w, bv1.x, bv1.y, bv1.z, bv1.w};
#pragma unroll
            for (int i = 0; i < 8; i++)
#pragma unroll
                for (int j = 0; j < 8; j++) acc[i][j] = fmaf(a[i], c[j], acc[i][j]);
        }
    }
    float bias[8];
#pragma unroll
    for (int j = 0; j < 8; j++) bias[j] = b[n0 + tx * 8 + j];
#pragma unroll
    for (int i = 0; i < 8; i++) {
        int row = m0 + ty * 8 + i;
#pragma unroll
        for (int j = 0; j < 8; j++)
            g_h[row * DD + n0 + tx * 8 + j] = acc[i][j] + bias[j];
    }
}

// ---------------------------------------------------------------------------
// K2 / K2b: fp64-accumulated squared norms
// ---------------------------------------------------------------------------
__global__ __launch_bounds__(256)
void k_cnorm(const float* __restrict__ cb) {
    int code = blockIdx.x * 8 + (threadIdx.x >> 5);
    int lane = threadIdx.x & 31;
    const float* row = cb + code * DD;
    double s = 0.0;
#pragma unroll
    for (int i = 0; i < DD / 32; i++) {
        double v = (double)row[lane + i * 32];
        s = fma(v, v, s);
    }
#pragma unroll
    for (int o = 16; o > 0; o >>= 1) s += __shfl_xor_sync(0xffffffffu, s, o);
    if (lane == 0) g_cnorm[code] = (float)s;
}

__global__ __launch_bounds__(256)
void k_hnorm() {
    int row  = blockIdx.x * 8 + (threadIdx.x >> 5);
    int lane = threadIdx.x & 31;
    const float* hr = g_h + (long)row * DD;
    double s = 0.0;
#pragma unroll
    for (int i = 0; i < DD / 32; i++) {
        double v = (double)hr[lane + i * 32];
        s = fma(v, v, s);
    }
#pragma unroll
    for (int o = 16; o > 0; o >>= 1) s += __shfl_xor_sync(0xffffffffu, s, o);
    if (lane == 0) g_hnorm[row] = (float)s;
}

// ---------------------------------------------------------------------------
// K3: hi-only TF32 tensor-core candidate scan. 1 MMA per tile (was 3),
//     chunk depth 32 (half the barriers), no lo arrays (half the fill/LDSM).
//     Exact-fp32 refine makes all final decisions; MARGIN covers scan noise.
// ---------------------------------------------------------------------------
__global__ __launch_bounds__(256, 2)
void k_scan_tc(const float* __restrict__ cb) {
    __shared__ float Hhi[128][36];
    __shared__ float Chi[128][36];
    __shared__ int   rowMinB[128];
    __shared__ int   s_cnt[128];
    __shared__ int   s_list[128][MAXC];

    const int tid  = threadIdx.x;
    const int lane = tid & 31;
    const int w    = tid >> 5;
    const int g    = lane >> 2;       // group 0..7
    const int tg   = lane & 3;        // thread-in-group 0..3
    const int mrow = (w & 3) * 32;    // warp row base (local)
    const int ncol = (w >> 2) * 64;   // warp code base (within tile)
    const int m0   = blockIdx.x * 128;

    if (tid < 128) { rowMinB[tid] = 0x7f800000; s_cnt[tid] = 0; }

    float tv1[4], tv2[4];
    unsigned tpk[4];
#pragma unroll
    for (int s = 0; s < 4; s++) { tv1[s] = CUDART_INF_F; tv2[s] = CUDART_INF_F; tpk[s] = 0; }

    float hnv[4];
#pragma unroll
    for (int s = 0; s < 4; s++) hnv[s] = g_hnorm[m0 + mrow + s * 8 + g];

    // smem fill: thread covers row fr, 16 consecutive d at col base fc
    const int fr = tid >> 1;
    const int fc = (tid & 1) * 16;

    // ldmatrix lane addressing (fixed per kernel)
    const int aRow = ((lane >> 3) & 1) * 8 + (lane & 7);
    const int aCol = ((lane >> 4) & 1) * 4;
    const int bRow = ((lane >> 4) & 1) * 8 + (lane & 7);
    const int bCol = ((lane >> 3) & 1) * 4;

    const unsigned shA0 = smem_u32(&Hhi[mrow + aRow][aCol]);
    const unsigned shA1 = shA0 + 16 * 36 * 4;
    const unsigned shB0 = smem_u32(&Chi[ncol + bRow][bCol]);

    for (int kt = 0; kt < KCODES; kt += 128) {
        float acc[2][8][4];
#pragma unroll
        for (int mt = 0; mt < 2; mt++)
#pragma unroll
            for (int nt = 0; nt < 8; nt++)
#pragma unroll
                for (int q = 0; q < 4; q++) acc[mt][nt][q] = 0.f;

        for (int ch = 0; ch < DD / 32; ch++) {
            int d0 = ch * 32;
            float4 hv[4], cv[4];
#pragma unroll
            for (int q = 0; q < 4; q++) {
                hv[q] = *(const float4*)&g_h[(m0 + fr) * DD + d0 + fc + q * 4];
                cv[q] = *(const float4*)&cb[(kt + fr) * DD + d0 + fc + q * 4];
            }
            __syncthreads();
#pragma unroll
            for (int q = 0; q < 4; q++) {
                Hhi[fr][fc + q * 4 + 0] = tf32hi(hv[q].x);
                Hhi[fr][fc + q * 4 + 1] = tf32hi(hv[q].y);
                Hhi[fr][fc + q * 4 + 2] = tf32hi(hv[q].z);
                Hhi[fr][fc + q * 4 + 3] = tf32hi(hv[q].w);
                Chi[fr][fc + q * 4 + 0] = tf32hi(cv[q].x);
                Chi[fr][fc + q * 4 + 1] = tf32hi(cv[q].y);
                Chi[fr][fc + q * 4 + 2] = tf32hi(cv[q].z);
                Chi[fr][fc + q * 4 + 3] = tf32hi(cv[q].w);
            }
            __syncthreads();
#pragma unroll
            for (int k8 = 0; k8 < 4; k8++) {
                const unsigned ko = k8 * 32;    // 8 k-values -> +32 bytes
                unsigned Ahi0[4], Ahi1[4];
                ldsm4(Ahi0, shA0 + ko);
                ldsm4(Ahi1, shA1 + ko);
#pragma unroll
                for (int ntp = 0; ntp < 4; ntp++) {
                    const unsigned no = ntp * 16 * 36 * 4;   // +16 codes
                    unsigned Bhi[4];
                    ldsm4(Bhi, shB0 + no + ko);
                    mma_tf32(acc[0][2 * ntp],     Ahi0, Bhi);
                    mma_tf32(acc[1][2 * ntp],     Ahi1, Bhi);
                    mma_tf32(acc[0][2 * ntp + 1], Ahi0, Bhi + 2);
                    mma_tf32(acc[1][2 * ntp + 1], Ahi1, Bhi + 2);
                }
            }
        }
        // epilogue: approx scores, streaming top-2 per row-slot
#pragma unroll
        for (int nt = 0; nt < 8; nt++) {
            int code0 = kt + ncol + nt * 8 + 2 * tg;
            float cn0 = g_cnorm[code0];
            float cn1 = g_cnorm[code0 + 1];
#pragma unroll
            for (int mt = 0; mt < 2; mt++) {
#pragma unroll
                for (int q = 0; q < 4; q++) {
                    int sl = mt * 2 + (q >> 1);
                    float cn = (q & 1) ? cn1 : cn0;
                    int   cd = code0 + (q & 1);
                    float s = fmaf(-2.f, acc[mt][nt][q], hnv[sl] + cn);
                    if (s < tv1[sl]) {
                        tv2[sl] = tv1[sl];
                        tpk[sl] = ((tpk[sl] & 0xffffu) << 16) | (unsigned)cd;
                        tv1[sl] = s;
                    } else if (s < tv2[sl]) {
                        tv2[sl] = s;
                        tpk[sl] = (tpk[sl] & 0xffffu) | ((unsigned)cd << 16);
                    }
                }
            }
        }
    }
    __syncthreads();
#pragma unroll
    for (int s = 0; s < 4; s++) {
        int rl = mrow + s * 8 + g;
        atomicMin(&rowMinB[rl], __float_as_int(tv1[s]));
    }
    __syncthreads();
#pragma unroll
    for (int s = 0; s < 4; s++) {
        int rl = mrow + s * 8 + g;
        float thr = __int_as_float(rowMinB[rl]) + MARGIN;
        if (tv1[s] <= thr) {
            int sl = atomicAdd(&s_cnt[rl], 1);
            if (sl < MAXC) s_list[rl][sl] = (int)(tpk[s] & 0xffffu);
        }
        if (tv2[s] <= thr) {
            int sl = atomicAdd(&s_cnt[rl], 1);
            if (sl < MAXC) s_list[rl][sl] = (int)(tpk[s] >> 16);
        }
    }
    __syncthreads();
    if (tid < 128) {
        int n = s_cnt[tid]; if (n > MAXC) n = MAXC;
        g_cand_cnt[m0 + tid] = n;
        for (int k = 0; k < n; k++) g_cand[m0 + tid][k] = s_list[tid][k];
    }
}

// ---------------------------------------------------------------------------
// K4: refine — exact round-4 numerics (unchanged, decision-making kernel)
// ---------------------------------------------------------------------------
__global__ __launch_bounds__(256)
void k_refine(const float* __restrict__ cb) {
    int row  = blockIdx.x * 8 + (threadIdx.x >> 5);
    int lane = threadIdx.x & 31;
    int n = g_cand_cnt[row];
    if (n <= 1) {
        if (lane == 0) g_idx[row] = (n == 1) ? g_cand[row][0] : 0;
        return;
    }
    float s  = CUDART_INF_F;
    int   bi = 0x7fffffff;
    if (lane < n) {
        int code = g_cand[row][lane];
        const float* hr = g_h + (long)row * DD;
        const float* er = cb + (long)code * DD;
        float acc = 0.f;
        for (int d = 0; d < DD; d++) acc = __fmaf_rn(hr[d], er[d], acc);
        float t = __fadd_rn(g_hnorm[row], g_cnorm[code]);
        s = __fmaf_rn(-2.f, acc, t);
        bi = code;
    }
#pragma unroll
    for (int off = 16; off >= 1; off >>= 1) {
        float ov = __shfl_xor_sync(0xffffffffu, s, off);
        int   oi = __shfl_xor_sync(0xffffffffu, bi, off);
        if (ov < s || (ov == s && oi < bi)) { s = ov; bi = oi; }
    }
    if (lane == 0) g_idx[row] = bi;
}

// ---------------------------------------------------------------------------
// K5: gather zq -> out, partial loss sums
// ---------------------------------------------------------------------------
__global__ __launch_bounds__(256)
void k_gather(const float* __restrict__ cb, float* __restrict__ out) {
    __shared__ float red[256];
    float lsum = 0.f;
    const int total = BT * DD;
    for (int e = blockIdx.x * 256 + threadIdx.x; e < total; e += NPART * 256) {
        int row = e >> 8;
        int d = e & (DD - 1);
        int c = g_idx[row];
        float zq = cb[c * DD + d];
        float hh = g_h[e];
        out[e] = zq;
        float df = zq - hh;
        lsum = fmaf(df, df, lsum);
    }
    red[threadIdx.x] = lsum;
    __syncthreads();
    for (int o = 128; o > 0; o >>= 1) {
        if (threadIdx.x < o) red[threadIdx.x] += red[threadIdx.x + o];
        __syncthreads();
    }
    if (threadIdx.x == 0) g_part[blockIdx.x] = red[0];
}

// ---------------------------------------------------------------------------
// K6: final loss reduce
// ---------------------------------------------------------------------------
__global__ __launch_bounds__(256)
void k_loss(float* __restrict__ out, int out_size) {
    __shared__ float red[256];
    float s = 0.f;
    for (int i = threadIdx.x; i < NPART; i += 256) s += g_part[i];
    red[threadIdx.x] = s;
    __syncthreads();
    for (int o = 128; o > 0; o >>= 1) {
        if (threadIdx.x < o) red[threadIdx.x] += red[threadIdx.x + o];
        __syncthreads();
    }
    if (threadIdx.x == 0)
        out[out_size - 1] = 1.25f * red[0] / (float)(BT * DD);
}

// ---------------------------------------------------------------------------
extern "C" void kernel_launch(void* const* d_in, const int* in_sizes, int n_in,
                              void* d_out, int out_size) {
    const float* x  = (const float*)d_in[0];   // [8,4096,1,512]
    const float* W  = (const float*)d_in[1];   // [512,256]
    const float* b  = (const float*)d_in[2];   // [256]
    const float* cb = (const float*)d_in[3];   // [8192,256]
    float* out = (float*)d_out;

    k_gemm_h<<<dim3(DD / 128, BT / 128), 256>>>(x, W, b);
    k_cnorm<<<KCODES / 8, 256>>>(cb);
    k_hnorm<<<BT / 8, 256>>>();
    k_scan_tc<<<BT / 128, 256>>>(cb);
    k_refine<<<BT / 8, 256>>>(cb);
    k_gather<<<NPART, 256>>>(cb, out);
    k_loss<<<1, 256>>>(out, out_size);
}